// round 1
// baseline (speedup 1.0000x reference)
#include <cuda_runtime.h>
#include <math.h>

#define H 4096
#define INV_SQRT_D (1.0f / 64.0f)

// ---------------- device scratch (allocation-free) ----------------
__device__ float g_q[H];
__device__ float g_k[H];     // already scaled by 1/sqrt(d)
__device__ float g_v[H];
__device__ float g_opre[H];  // Wo@x + bo (pre-sigmoid)
__device__ float g_dots[2];  // wi.x, wf.x
__device__ float g_sc[3];    // i_gate, f_gate, 1/denom

// ---------------- reductions ----------------
__device__ __forceinline__ float warp_reduce(float v) {
    #pragma unroll
    for (int o = 16; o > 0; o >>= 1)
        v += __shfl_down_sync(0xffffffffu, v, o);
    return v;
}

// block reduce for blockDim.x == 256 (8 warps)
__device__ __forceinline__ float block_reduce_256(float v) {
    __shared__ float s[8];
    int lane = threadIdx.x & 31;
    int wid  = threadIdx.x >> 5;
    v = warp_reduce(v);
    if (lane == 0) s[wid] = v;
    __syncthreads();
    if (wid == 0) {
        v = (lane < 8) ? s[lane] : 0.0f;
        v = warp_reduce(v);
    }
    return v; // valid in warp 0
}

// block reduce for blockDim.x == 1024 (32 warps)
__device__ __forceinline__ float block_reduce_1024(float v) {
    __shared__ float s[32];
    int lane = threadIdx.x & 31;
    int wid  = threadIdx.x >> 5;
    v = warp_reduce(v);
    if (lane == 0) s[wid] = v;
    __syncthreads();
    if (wid == 0) {
        v = s[lane];
        v = warp_reduce(v);
    }
    return v; // valid in warp 0
}

// ---------------- kernel A: all matvecs + scalar-gate dots ----------------
// grid = 4*H + 2 blocks, 256 threads each. Block b computes one row-dot.
__global__ void __launch_bounds__(256)
matvec_kernel(const float* __restrict__ x,
              const float* __restrict__ Wq, const float* __restrict__ Wk,
              const float* __restrict__ Wv, const float* __restrict__ Wo,
              const float* __restrict__ bq, const float* __restrict__ bk,
              const float* __restrict__ bv, const float* __restrict__ bo,
              const float* __restrict__ wi, const float* __restrict__ wf) {
    int row = blockIdx.x;
    const float* wrow;
    if      (row <     H) wrow = Wq + (size_t) row          * H;
    else if (row < 2 * H) wrow = Wk + (size_t)(row -   H)   * H;
    else if (row < 3 * H) wrow = Wv + (size_t)(row - 2*H)   * H;
    else if (row < 4 * H) wrow = Wo + (size_t)(row - 3*H)   * H;
    else                  wrow = (row == 4 * H) ? wi : wf;

    const float4* w4 = (const float4*)wrow;
    const float4* x4 = (const float4*)x;
    int tid = threadIdx.x;

    float sum = 0.0f;
    #pragma unroll
    for (int i = 0; i < (H / 4) / 256; i++) {   // 4 iters
        int idx = tid + i * 256;
        float4 w  = __ldcs(&w4[idx]);           // streaming: don't pollute L1
        float4 xv = x4[idx];                    // cached: x reused across blocks
        sum += w.x * xv.x + w.y * xv.y + w.z * xv.z + w.w * xv.w;
    }
    sum = block_reduce_256(sum);

    if (threadIdx.x == 0) {
        if      (row <     H) g_q[row]          = sum + bq[row];
        else if (row < 2 * H) g_k[row -   H]    = (sum + bk[row - H]) * INV_SQRT_D;
        else if (row < 3 * H) g_v[row - 2*H]    = sum + bv[row - 2*H];
        else if (row < 4 * H) g_opre[row - 3*H] = sum + bo[row - 3*H];
        else                  g_dots[row - 4*H] = sum;
    }
}

// ---------------- kernel B: gates, n update, denom ----------------
// 1 block, 1024 threads.
__global__ void __launch_bounds__(1024)
gate_n_kernel(const float* __restrict__ n_prev,
              const float* __restrict__ bi, const float* __restrict__ bf,
              float* __restrict__ out_n) {
    __shared__ float s_ig, s_fg;
    int tid = threadIdx.x;
    if (tid == 0) {
        s_ig = expf(g_dots[0] + bi[0]);
        s_fg = 1.0f / (1.0f + expf(-(g_dots[1] + bf[0])));
    }
    __syncthreads();
    float ig = s_ig, fg = s_fg;

    float dot = 0.0f;
    #pragma unroll
    for (int i = 0; i < H / 1024; i++) {        // 4 iters
        int j = tid + i * 1024;
        float nj = fg * n_prev[j] + ig * g_k[j];
        out_n[j] = nj;
        dot += nj * g_q[j];
    }
    dot = block_reduce_1024(dot);
    if (tid == 0) {
        float denom = fmaxf(fabsf(dot), 1.0f);
        g_sc[0] = ig;
        g_sc[1] = fg;
        g_sc[2] = 1.0f / denom;
    }
}

// ---------------- kernel C: C update + fused readout + output gate ----------------
// grid = H blocks, 256 threads. Block r: new C row r, dot with q, h[r].
__global__ void __launch_bounds__(256)
update_kernel(const float* __restrict__ C_prev,
              float* __restrict__ out_h, float* __restrict__ out_C) {
    int row = blockIdx.x;
    int tid = threadIdx.x;

    float ig = g_sc[0], fg = g_sc[1], invden = g_sc[2];
    float ivr = ig * g_v[row];

    const float4* cp4 = (const float4*)(C_prev + (size_t)row * H);
    float4*       co4 = (float4*)      (out_C  + (size_t)row * H);
    const float4* k4  = (const float4*)g_k;
    const float4* q4  = (const float4*)g_q;

    float dot = 0.0f;
    #pragma unroll
    for (int i = 0; i < (H / 4) / 256; i++) {   // 4 iters
        int idx = tid + i * 256;
        float4 c  = __ldcs(&cp4[idx]);          // streaming read of C_prev
        float4 kk = k4[idx];                    // L1-resident
        float4 qq = q4[idx];                    // L1-resident
        float4 cn;
        cn.x = fg * c.x + ivr * kk.x;
        cn.y = fg * c.y + ivr * kk.y;
        cn.z = fg * c.z + ivr * kk.z;
        cn.w = fg * c.w + ivr * kk.w;
        __stcs(&co4[idx], cn);                  // streaming write of new C
        dot += cn.x * qq.x + cn.y * qq.y + cn.z * qq.z + cn.w * qq.w;
    }
    dot = block_reduce_256(dot);
    if (tid == 0) {
        float h_tilde = dot * invden;
        float o = 1.0f / (1.0f + expf(-g_opre[row]));
        out_h[row] = o * h_tilde;
    }
}

// ---------------- launcher ----------------
extern "C" void kernel_launch(void* const* d_in, const int* in_sizes, int n_in,
                              void* d_out, int out_size) {
    const float* x      = (const float*)d_in[0];
    // d_in[1] = h_prev (unused by mLSTM math)
    const float* C_prev = (const float*)d_in[2];
    const float* n_prev = (const float*)d_in[3];
    const float* Wq     = (const float*)d_in[4];
    const float* Wk     = (const float*)d_in[5];
    const float* Wv     = (const float*)d_in[6];
    const float* Wo     = (const float*)d_in[7];
    const float* bq     = (const float*)d_in[8];
    const float* bk     = (const float*)d_in[9];
    const float* bv     = (const float*)d_in[10];
    const float* bo     = (const float*)d_in[11];
    const float* wi     = (const float*)d_in[12];
    const float* bi     = (const float*)d_in[13];
    const float* wf     = (const float*)d_in[14];
    const float* bf     = (const float*)d_in[15];

    float* out   = (float*)d_out;
    float* out_h = out;                      // [H]
    float* out_C = out + H;                  // [H, H]
    float* out_n = out + H + (size_t)H * H;  // [H]

    matvec_kernel<<<4 * H + 2, 256>>>(x, Wq, Wk, Wv, Wo, bq, bk, bv, bo, wi, wf);
    gate_n_kernel<<<1, 1024>>>(n_prev, bi, bf, out_n);
    update_kernel<<<H, 256>>>(C_prev, out_h, out_C);
}